// round 4
// baseline (speedup 1.0000x reference)
#include <cuda_runtime.h>
#include <cuda_bf16.h>
#include <math.h>

// ---------------- problem constants ----------------
#define D_MODEL   512
#define HEADS     8
#define DH        64
#define BATCH     32
#define S_CURR    128
#define N_MASK    16
#define GRID_CNT  40000
#define N_CAND    39998          // GRID_CNT - 2
#define M_GATH    (BATCH * N_MASK)   // 512 rows of gathered output

// ---------------- scratch (static device memory; no allocs allowed) -------
__device__ float g_curr[BATCH * S_CURR * D_MODEL]; // 32*128*512  (8 MB)
__device__ float g_qin [M_GATH * D_MODEL];         // 512*512
__device__ float g_K   [BATCH * S_CURR * D_MODEL]; // 8 MB
__device__ float g_V   [BATCH * S_CURR * D_MODEL]; // 8 MB
__device__ float g_Qm  [M_GATH * D_MODEL];
__device__ float g_att [M_GATH * D_MODEL];
__device__ float g_hyb [M_GATH * D_MODEL];
__device__ float g_lse [M_GATH];

// ---------------- positional embedding (matches numpy formula) ------------
__device__ __forceinline__ float pe_val(int pos, int d) {
    // div_term[i] = exp( (2i) * -(ln(10000)/512) ), pe[:,2i]=sin, pe[:,2i+1]=cos
    const float c = -9.210340371976184f / (float)D_MODEL; // -ln(10000)/512
    int i2 = d & ~1;
    float freq = expf((float)i2 * c);
    float arg = (float)pos * freq;
    return (d & 1) ? cosf(arg) : sinf(arg);
}

// ---------------- kernel 1: curr = emb[idx] + pe --------------------------
__global__ void build_curr_kernel(const int* __restrict__ idx,
                                  const float* __restrict__ emb) {
    int e = blockIdx.x * blockDim.x + threadIdx.x;   // 0 .. 32*128*512-1
    if (e >= BATCH * S_CURR * D_MODEL) return;
    int d   = e & (D_MODEL - 1);
    int s   = (e >> 9) & (S_CURR - 1);
    int bs  = e >> 9;                                 // b*128+s
    int g   = idx[bs];
    g_curr[e] = emb[(long long)g * D_MODEL + d] + pe_val(s, d);
}

// ---------------- kernel 2: qin = emb[idx[mask_pos]] + pe -----------------
__global__ void build_qin_kernel(const int* __restrict__ idx,
                                 const int* __restrict__ mask_pos,
                                 const float* __restrict__ emb) {
    int e = blockIdx.x * blockDim.x + threadIdx.x;   // 0 .. 512*512-1
    if (e >= M_GATH * D_MODEL) return;
    int d = e & (D_MODEL - 1);
    int r = e >> 9;                                   // b*16+i
    int b = r >> 4;
    int s = mask_pos[r];                              // position in [0,128)
    int g = idx[b * S_CURR + s];
    g_qin[e] = emb[(long long)g * D_MODEL + d] + pe_val(s, d);
}

// ---------------- generic GEMM: C[M,N] = A[M,K] * B[N,K]^T + bias ---------
// BM=128 BN=64 BK=16, 256 threads, 8x4 microtile. M % 128 == 0, K % 16 == 0.
// N may be ragged (bounds-checked).
__global__ __launch_bounds__(256)
void gemm_tn_kernel(const float* __restrict__ A,
                    const float* __restrict__ B,
                    const float* __restrict__ bias,
                    float* __restrict__ C,
                    int M, int N, int K) {
    __shared__ float As[16][128];
    __shared__ float Bs[16][64];

    const int tid = threadIdx.x;
    const int ty  = tid >> 4;     // 0..15 -> rows ty*8..ty*8+7
    const int tx  = tid & 15;     // 0..15 -> cols tx*4..tx*4+3
    const int rowBase = blockIdx.y * 128;
    const int nBase   = blockIdx.x * 64;

    const int lrow  = tid >> 2;        // 0..63
    const int lcol4 = (tid & 3) * 4;   // 0,4,8,12

    float acc[8][4];
#pragma unroll
    for (int i = 0; i < 8; i++)
#pragma unroll
        for (int j = 0; j < 4; j++) acc[i][j] = 0.f;

    for (int k0 = 0; k0 < K; k0 += 16) {
        // global loads
        float4 av0 = *(const float4*)&A[(long long)(rowBase + lrow)      * K + k0 + lcol4];
        float4 av1 = *(const float4*)&A[(long long)(rowBase + lrow + 64) * K + k0 + lcol4];
        int gn = nBase + lrow;
        float4 bv = make_float4(0.f, 0.f, 0.f, 0.f);
        if (gn < N) bv = *(const float4*)&B[(long long)gn * K + k0 + lcol4];

        __syncthreads();   // protect previous tile reads
        As[lcol4 + 0][lrow] = av0.x;
        As[lcol4 + 1][lrow] = av0.y;
        As[lcol4 + 2][lrow] = av0.z;
        As[lcol4 + 3][lrow] = av0.w;
        As[lcol4 + 0][lrow + 64] = av1.x;
        As[lcol4 + 1][lrow + 64] = av1.y;
        As[lcol4 + 2][lrow + 64] = av1.z;
        As[lcol4 + 3][lrow + 64] = av1.w;
        Bs[lcol4 + 0][lrow] = bv.x;
        Bs[lcol4 + 1][lrow] = bv.y;
        Bs[lcol4 + 2][lrow] = bv.z;
        Bs[lcol4 + 3][lrow] = bv.w;
        __syncthreads();

#pragma unroll
        for (int k = 0; k < 16; k++) {
            float4 a0 = *(const float4*)&As[k][ty * 8];
            float4 a1 = *(const float4*)&As[k][ty * 8 + 4];
            float4 b0 = *(const float4*)&Bs[k][tx * 4];
            float ar[8] = {a0.x, a0.y, a0.z, a0.w, a1.x, a1.y, a1.z, a1.w};
            float br[4] = {b0.x, b0.y, b0.z, b0.w};
#pragma unroll
            for (int i = 0; i < 8; i++)
#pragma unroll
                for (int j = 0; j < 4; j++)
                    acc[i][j] = fmaf(ar[i], br[j], acc[i][j]);
        }
    }

    // epilogue
#pragma unroll
    for (int i = 0; i < 8; i++) {
        int row = rowBase + ty * 8 + i;
#pragma unroll
        for (int j = 0; j < 4; j++) {
            int col = nBase + tx * 4 + j;
            if (col < N) {
                float v = acc[i][j];
                if (bias) v += bias[col];
                C[(long long)row * N + col] = v;
            }
        }
    }
}

// ---------------- attention (per b,h): Qm(16,64) x K(128,64) softmax x V --
__global__ __launch_bounds__(128)
void attn_kernel() {
    const int b = blockIdx.x >> 3;
    const int h = blockIdx.x & 7;
    const int tid = threadIdx.x;   // 0..127

    __shared__ float Qs[16][64];
    __shared__ float KVs[128][65];   // padded
    __shared__ float Ss[16][128];

    // load Q
    for (int e = tid; e < 16 * 64; e += 128) {
        int q = e >> 6, d = e & 63;
        Qs[q][d] = g_Qm[(b * 16 + q) * D_MODEL + h * DH + d];
    }
    // load K
    for (int e = tid; e < 128 * 64; e += 128) {
        int s = e >> 6, d = e & 63;
        KVs[s][d] = g_K[(b * S_CURR + s) * D_MODEL + h * DH + d];
    }
    __syncthreads();

    // phase 1: scores, thread t owns key-column t
    {
        float acc[16];
#pragma unroll
        for (int q = 0; q < 16; q++) acc[q] = 0.f;
#pragma unroll 8
        for (int d = 0; d < 64; d++) {
            float kv = KVs[tid][d];
#pragma unroll
            for (int q = 0; q < 16; q++) acc[q] = fmaf(Qs[q][d], kv, acc[q]);
        }
#pragma unroll
        for (int q = 0; q < 16; q++) Ss[q][tid] = acc[q];
    }
    __syncthreads();

    // phase 2: softmax per q-row (warp w does rows w*4..w*4+3), and V load
    {
        int w = tid >> 5, lane = tid & 31;
        for (int r = 0; r < 4; r++) {
            int q = w * 4 + r;
            float v[4];
#pragma unroll
            for (int j = 0; j < 4; j++) v[j] = Ss[q][lane + 32 * j];
            float m = fmaxf(fmaxf(v[0], v[1]), fmaxf(v[2], v[3]));
#pragma unroll
            for (int off = 16; off > 0; off >>= 1)
                m = fmaxf(m, __shfl_xor_sync(0xffffffffu, m, off));
            float s = 0.f;
#pragma unroll
            for (int j = 0; j < 4; j++) s += expf(v[j] - m);
#pragma unroll
            for (int off = 16; off > 0; off >>= 1)
                s += __shfl_xor_sync(0xffffffffu, s, off);
            float inv = 1.f / s;
#pragma unroll
            for (int j = 0; j < 4; j++) Ss[q][lane + 32 * j] = expf(v[j] - m) * inv;
        }
    }
    // load V (overwrite KVs; K reads finished at the last sync)
    for (int e = tid; e < 128 * 64; e += 128) {
        int s = e >> 6, d = e & 63;
        KVs[s][d] = g_V[(b * S_CURR + s) * D_MODEL + h * DH + d];
    }
    __syncthreads();

    // phase 3: out = P @ V. thread -> (qb = tid/64, d = tid%64)
    {
        int d = tid & 63;
        int qb = tid >> 6;
#pragma unroll
        for (int qq = 0; qq < 8; qq++) {
            int q = qq * 2 + qb;
            float o = 0.f;
#pragma unroll 8
            for (int t = 0; t < 128; t++) o = fmaf(Ss[q][t], KVs[t][d], o);
            g_att[(b * 16 + q) * D_MODEL + h * DH + d] = o;
        }
    }
}

// ---------------- tanh in place on g_att ----------------------------------
__global__ void tanh_kernel() {
    int e = blockIdx.x * blockDim.x + threadIdx.x;
    if (e < M_GATH * D_MODEL) g_att[e] = tanhf(g_att[e]);
}

// ---------------- logsumexp per output row --------------------------------
__global__ __launch_bounds__(256)
void lse_kernel(const float* __restrict__ out) {
    const int row = blockIdx.x;
    const float* x = out + (long long)row * N_CAND;
    float m = -INFINITY, s = 0.f;
    for (int c = threadIdx.x; c < N_CAND; c += 256) {
        float v = x[c];
        if (v <= m) {
            s += expf(v - m);
        } else {
            s = s * expf(m - v) + 1.f;
            m = v;
        }
    }
    __shared__ float sm[256], ssum[256];
    sm[threadIdx.x] = m;
    ssum[threadIdx.x] = s;
    __syncthreads();
    for (int stride = 128; stride > 0; stride >>= 1) {
        if (threadIdx.x < stride) {
            float m1 = sm[threadIdx.x],        s1 = ssum[threadIdx.x];
            float m2 = sm[threadIdx.x+stride], s2 = ssum[threadIdx.x+stride];
            float M = fmaxf(m1, m2);
            float S = s1 * expf(m1 - M) + s2 * expf(m2 - M);
            sm[threadIdx.x] = M; ssum[threadIdx.x] = S;
        }
        __syncthreads();
    }
    if (threadIdx.x == 0) g_lse[row] = sm[0] + logf(ssum[0]);
}

// ---------------- subtract lse --------------------------------------------
__global__ void sub_kernel(float* __restrict__ out) {
    int row = blockIdx.y;
    int c = blockIdx.x * blockDim.x + threadIdx.x;
    if (c < N_CAND) out[(long long)row * N_CAND + c] -= g_lse[row];
}

// ---------------- launch ---------------------------------------------------
extern "C" void kernel_launch(void* const* d_in, const int* in_sizes, int n_in,
                              void* d_out, int out_size) {
    // input order (metadata): 0 hist_traj_grid, 1 userId, 2 mask_pos,
    // 3 mask_curr_traj_grid, 4 aggregator_hist_traj_grid, 5 emb,
    // 6..11 h_*, 12 c_wq, 13 c_bq, 14 c_wk, 15 c_bk, 16 c_wv, 17 c_bv,
    // 18..23 x_*, 24 t2_w, 25 t2_b
    const int*   mask_pos  = (const int*)d_in[2];
    const int*   mask_curr = (const int*)d_in[3];
    const float* emb       = (const float*)d_in[5];
    const float* c_wq      = (const float*)d_in[12];
    const float* c_bq      = (const float*)d_in[13];
    const float* c_wk      = (const float*)d_in[14];
    const float* c_bk      = (const float*)d_in[15];
    const float* c_wv      = (const float*)d_in[16];
    const float* c_bv      = (const float*)d_in[17];
    const float* t2_w      = (const float*)d_in[24];
    const float* t2_b      = (const float*)d_in[25];
    float* out = (float*)d_out;

    float *p_curr, *p_qin, *p_K, *p_V, *p_Qm, *p_att, *p_hyb;
    cudaGetSymbolAddress((void**)&p_curr, g_curr);
    cudaGetSymbolAddress((void**)&p_qin,  g_qin);
    cudaGetSymbolAddress((void**)&p_K,    g_K);
    cudaGetSymbolAddress((void**)&p_V,    g_V);
    cudaGetSymbolAddress((void**)&p_Qm,   g_Qm);
    cudaGetSymbolAddress((void**)&p_att,  g_att);
    cudaGetSymbolAddress((void**)&p_hyb,  g_hyb);

    // 1) embeddings + positional encodings
    build_curr_kernel<<<(BATCH * S_CURR * D_MODEL) / 256, 256>>>(mask_curr, emb);
    build_qin_kernel<<<(M_GATH * D_MODEL) / 256, 256>>>(mask_curr, mask_pos, emb);

    // 2) K, V projections over all 4096 positions; Q only at masked rows
    {
        dim3 gridKV(D_MODEL / 64, (BATCH * S_CURR) / 128);
        gemm_tn_kernel<<<gridKV, 256>>>(p_curr, c_wk, c_bk, p_K,
                                        BATCH * S_CURR, D_MODEL, D_MODEL);
        gemm_tn_kernel<<<gridKV, 256>>>(p_curr, c_wv, c_bv, p_V,
                                        BATCH * S_CURR, D_MODEL, D_MODEL);
        dim3 gridQ(D_MODEL / 64, M_GATH / 128);
        gemm_tn_kernel<<<gridQ, 256>>>(p_qin, c_wq, c_bq, p_Qm,
                                       M_GATH, D_MODEL, D_MODEL);
    }

    // 3) attention (no 1/sqrt(d) scaling in reference)
    attn_kernel<<<BATCH * HEADS, 128>>>();

    // 4) hyb = tanh(att) @ t2_w^T + t2_b
    tanh_kernel<<<(M_GATH * D_MODEL) / 256, 256>>>();
    {
        dim3 grid(D_MODEL / 64, M_GATH / 128);
        gemm_tn_kernel<<<grid, 256>>>(p_att, t2_w, t2_b, p_hyb,
                                      M_GATH, D_MODEL, D_MODEL);
    }

    // 5) scores = hyb @ emb[2:]^T   (the 21 GFLOP GEMM)
    {
        dim3 grid((N_CAND + 63) / 64, M_GATH / 128);
        gemm_tn_kernel<<<grid, 256>>>(p_hyb, emb + 2 * D_MODEL, nullptr, out,
                                      M_GATH, N_CAND, D_MODEL);
    }

    // 6) log_softmax
    lse_kernel<<<M_GATH, 256>>>(out);
    {
        dim3 grid((N_CAND + 255) / 256, M_GATH);
        sub_kernel<<<grid, 256>>>(out);
    }
}

// round 10
// speedup vs baseline: 2.8487x; 2.8487x over previous
#include <cuda_runtime.h>
#include <cuda_bf16.h>
#include <math.h>
#include <stdint.h>

// ---------------- problem constants ----------------
#define D_MODEL   512
#define HEADS     8
#define DH        64
#define BATCH     32
#define S_CURR    128
#define N_MASK    16
#define GRID_CNT  40000
#define N_CAND    39998
#define M_GATH    (BATCH * N_MASK)   // 512

// ---------------- scratch ----------------
__device__ float g_curr[BATCH * S_CURR * D_MODEL];
__device__ float g_qin [M_GATH * D_MODEL];
__device__ float g_K   [BATCH * S_CURR * D_MODEL];
__device__ float g_V   [BATCH * S_CURR * D_MODEL];
__device__ float g_Qm  [M_GATH * D_MODEL];
__device__ float g_att [M_GATH * D_MODEL];
__device__ float g_hyb [M_GATH * D_MODEL];
__device__ float g_lse [M_GATH];

// =======================================================================
// helpers
// =======================================================================
__device__ __forceinline__ uint32_t smem_u32(const void* p) {
    uint32_t a;
    asm("{ .reg .u64 t; cvta.to.shared.u64 t, %1; cvt.u32.u64 %0, t; }"
        : "=r"(a) : "l"(p));
    return a;
}

#define LDSM4(r0, r1, r2, r3, addr) \
    asm volatile("ldmatrix.sync.aligned.m8n8.x4.shared.b16 {%0,%1,%2,%3}, [%4];" \
                 : "=r"(r0), "=r"(r1), "=r"(r2), "=r"(r3) : "r"(addr))

#define MMA16816(d, a, b) \
    asm volatile("mma.sync.aligned.m16n8k16.row.col.f32.bf16.bf16.f32 " \
                 "{%0,%1,%2,%3}, {%4,%5,%6,%7}, {%8,%9}, {%0,%1,%2,%3};" \
                 : "+f"((d)[0]), "+f"((d)[1]), "+f"((d)[2]), "+f"((d)[3]) \
                 : "r"((a)[0]), "r"((a)[1]), "r"((a)[2]), "r"((a)[3]), \
                   "r"((b)[0]), "r"((b)[1]))

// =======================================================================
// positional embedding
// =======================================================================
__device__ __forceinline__ float pe_val(int pos, int d) {
    const float c = -9.210340371976184f / (float)D_MODEL;
    int i2 = d & ~1;
    float freq = expf((float)i2 * c);
    float arg = (float)pos * freq;
    return (d & 1) ? cosf(arg) : sinf(arg);
}

__global__ void build_curr_kernel(const int* __restrict__ idx,
                                  const float* __restrict__ emb) {
    int e = blockIdx.x * blockDim.x + threadIdx.x;
    if (e >= BATCH * S_CURR * D_MODEL) return;
    int d  = e & (D_MODEL - 1);
    int s  = (e >> 9) & (S_CURR - 1);
    int bs = e >> 9;
    int g  = idx[bs];
    g_curr[e] = emb[(long long)g * D_MODEL + d] + pe_val(s, d);
}

__global__ void build_qin_kernel(const int* __restrict__ idx,
                                 const int* __restrict__ mask_pos,
                                 const float* __restrict__ emb) {
    int e = blockIdx.x * blockDim.x + threadIdx.x;
    if (e >= M_GATH * D_MODEL) return;
    int d = e & (D_MODEL - 1);
    int r = e >> 9;
    int b = r >> 4;
    int s = mask_pos[r];
    int g = idx[b * S_CURR + s];
    g_qin[e] = emb[(long long)g * D_MODEL + d] + pe_val(s, d);
}

// =======================================================================
// HMMA (mma.sync) GEMM: C[M,N] = A[M,K=512] * B[N,K=512]^T (+bias)
// fp32 split into bf16 hi/lo on the fly; 3-term product restores ~fp32
// accuracy. CTA tile 128x128, K-chunk 32 fp32, 2-stage smem pipeline,
// register prefetch, 256 threads (8 warps, 4x2, warp tile 32x64).
// M must be a multiple of 128; N ragged (guarded).
// =======================================================================
#define NCHUNK   16            // 512 / 32
#define LDT      40            // bf16 elems per tile row (32 + 8 pad)
#define LDTB     80            // bytes per tile row
#define TILE_SZ  (128 * LDTB)  // 10240 B
#define OFF_AHI  0
#define OFF_ALO  (1 * TILE_SZ)
#define OFF_BHI  (2 * TILE_SZ)
#define OFF_BLO  (3 * TILE_SZ)
#define STAGE_SZ (4 * TILE_SZ) // 40960 B
#define GSMEM    (2 * STAGE_SZ)

__device__ __forceinline__ void ldg_chunk(const float* __restrict__ A,
                                          const float* __restrict__ B,
                                          int mBase, int nBase, int Nrows,
                                          int kt, int lrow, int lf4,
                                          float4 av[4], float4 bv[4]) {
    const float* ap = A + (long long)(mBase + lrow) * 512 + kt * 32;
#pragma unroll
    for (int i = 0; i < 4; i++) av[i] = *(const float4*)(ap + (lf4 + i) * 4);
    int gn = nBase + lrow;
    if (gn < Nrows) {
        const float* bp = B + (long long)gn * 512 + kt * 32;
#pragma unroll
        for (int i = 0; i < 4; i++) bv[i] = *(const float4*)(bp + (lf4 + i) * 4);
    } else {
#pragma unroll
        for (int i = 0; i < 4; i++) bv[i] = make_float4(0.f, 0.f, 0.f, 0.f);
    }
}

__device__ __forceinline__ void sts_split(char* st, int offHi, int offLo,
                                          int lrow, int lf4, const float4* v) {
#pragma unroll
    for (int i = 0; i < 4; i++) {
        float4 x = v[i];
        __nv_bfloat162 h01 = __floats2bfloat162_rn(x.x, x.y);
        __nv_bfloat162 h23 = __floats2bfloat162_rn(x.z, x.w);
        float lx = x.x - __bfloat162float(h01.x);
        float ly = x.y - __bfloat162float(h01.y);
        float lz = x.z - __bfloat162float(h23.x);
        float lw = x.w - __bfloat162float(h23.y);
        __nv_bfloat162 l01 = __floats2bfloat162_rn(lx, ly);
        __nv_bfloat162 l23 = __floats2bfloat162_rn(lz, lw);
        int boff = lrow * LDTB + (lf4 + i) * 8;
        *(uint2*)(st + offHi + boff) =
            make_uint2(*reinterpret_cast<unsigned*>(&h01),
                       *reinterpret_cast<unsigned*>(&h23));
        *(uint2*)(st + offLo + boff) =
            make_uint2(*reinterpret_cast<unsigned*>(&l01),
                       *reinterpret_cast<unsigned*>(&l23));
    }
}

__global__ __launch_bounds__(256, 1)
void gemm_mma_kernel(const float* __restrict__ A,
                     const float* __restrict__ B,
                     const float* __restrict__ bias,
                     float* __restrict__ C,
                     int Nrows, int ldc)
{
    extern __shared__ char sm[];
    const uint32_t smb = smem_u32(sm);
    const int tid  = threadIdx.x;
    const int lane = tid & 31;
    const int wid  = tid >> 5;
    const int mBase = blockIdx.x * 128;
    const int nBase = blockIdx.y * 128;
    const int mW = (wid & 3) * 32;     // warp m offset in tile
    const int nW = (wid >> 2) * 64;    // warp n offset in tile
    const int lrow = tid >> 1;         // loader row 0..127
    const int lf4  = (tid & 1) * 4;    // loader float4 base (0 or 4)
    const uint32_t laneOff = ((lane & 15) * LDT + (lane >> 4) * 8) * 2;

    float acc[2][8][4];
#pragma unroll
    for (int mf = 0; mf < 2; mf++)
#pragma unroll
        for (int nf = 0; nf < 8; nf++)
#pragma unroll
            for (int j = 0; j < 4; j++) acc[mf][nf][j] = 0.f;

    // prologue: chunk 0 -> stage 0
    {
        float4 av[4], bv[4];
        ldg_chunk(A, B, mBase, nBase, Nrows, 0, lrow, lf4, av, bv);
        sts_split(sm, OFF_AHI, OFF_ALO, lrow, lf4, av);
        sts_split(sm, OFF_BHI, OFF_BLO, lrow, lf4, bv);
        __syncthreads();
    }

#pragma unroll 1
    for (int kt = 0; kt < NCHUNK; kt++) {
        const int cur = kt & 1;
        float4 av[4], bv[4];
        if (kt < NCHUNK - 1)
            ldg_chunk(A, B, mBase, nBase, Nrows, kt + 1, lrow, lf4, av, bv);

        const uint32_t sOff = cur * STAGE_SZ;
#pragma unroll
        for (int p = 0; p < 3; p++) {
            uint32_t aT = smb + sOff + (p == 2 ? OFF_ALO : OFF_AHI) + mW * LDTB + laneOff;
            uint32_t bT = smb + sOff + (p == 1 ? OFF_BLO : OFF_BHI) + nW * LDTB + laneOff;
#pragma unroll
            for (int ks = 0; ks < 2; ks++) {
                uint32_t a[2][4];
                LDSM4(a[0][0], a[0][1], a[0][2], a[0][3], aT + ks * 32);
                LDSM4(a[1][0], a[1][1], a[1][2], a[1][3], aT + 16 * LDTB + ks * 32);
                uint32_t b[8][2];
#pragma unroll
                for (int nq = 0; nq < 4; nq++) {
                    uint32_t r0, r1, r2, r3;
                    LDSM4(r0, r1, r2, r3, bT + nq * 16 * LDTB + ks * 32);
                    b[2 * nq][0] = r0;  b[2 * nq][1] = r2;
                    b[2 * nq + 1][0] = r1;  b[2 * nq + 1][1] = r3;
                }
#pragma unroll
                for (int mf = 0; mf < 2; mf++)
#pragma unroll
                    for (int nf = 0; nf < 8; nf++)
                        MMA16816(acc[mf][nf], a[mf], b[nf]);
            }
        }

        if (kt < NCHUNK - 1) {
            char* st = sm + (cur ^ 1) * STAGE_SZ;
            sts_split(st, OFF_AHI, OFF_ALO, lrow, lf4, av);
            sts_split(st, OFF_BHI, OFF_BLO, lrow, lf4, bv);
            __syncthreads();
        }
    }

    // epilogue
    const int r0l = lane >> 2;
    const int c0l = (lane & 3) * 2;
#pragma unroll
    for (int mf = 0; mf < 2; mf++) {
#pragma unroll
        for (int nf = 0; nf < 8; nf++) {
            int row = mBase + mW + mf * 16 + r0l;
            int col = nBase + nW + nf * 8 + c0l;
            float* cp0 = C + (long long)row * ldc;
            float* cp1 = C + (long long)(row + 8) * ldc;
            if (col + 1 < Nrows) {
                float b0 = bias ? bias[col] : 0.f;
                float b1 = bias ? bias[col + 1] : 0.f;
                *(float2*)(cp0 + col) = make_float2(acc[mf][nf][0] + b0,
                                                    acc[mf][nf][1] + b1);
                *(float2*)(cp1 + col) = make_float2(acc[mf][nf][2] + b0,
                                                    acc[mf][nf][3] + b1);
            } else if (col < Nrows) {
                float b0 = bias ? bias[col] : 0.f;
                cp0[col] = acc[mf][nf][0] + b0;
                cp1[col] = acc[mf][nf][2] + b0;
            }
        }
    }
}

// =======================================================================
// attention (per b,h): Qm(16,64) x K(128,64) -> softmax -> x V
// =======================================================================
__global__ __launch_bounds__(128)
void attn_kernel() {
    const int b = blockIdx.x >> 3;
    const int h = blockIdx.x & 7;
    const int tid = threadIdx.x;

    __shared__ float Qs[16][64];
    __shared__ float KVs[128][65];
    __shared__ float Ss[16][128];

    for (int e = tid; e < 16 * 64; e += 128) {
        int q = e >> 6, d = e & 63;
        Qs[q][d] = g_Qm[(b * 16 + q) * D_MODEL + h * DH + d];
    }
    for (int e = tid; e < 128 * 64; e += 128) {
        int s = e >> 6, d = e & 63;
        KVs[s][d] = g_K[(b * S_CURR + s) * D_MODEL + h * DH + d];
    }
    __syncthreads();

    {
        float acc[16];
#pragma unroll
        for (int q = 0; q < 16; q++) acc[q] = 0.f;
#pragma unroll 8
        for (int d = 0; d < 64; d++) {
            float kv = KVs[tid][d];
#pragma unroll
            for (int q = 0; q < 16; q++) acc[q] = fmaf(Qs[q][d], kv, acc[q]);
        }
#pragma unroll
        for (int q = 0; q < 16; q++) Ss[q][tid] = acc[q];
    }
    __syncthreads();

    {
        int w = tid >> 5, lane = tid & 31;
        for (int r = 0; r < 4; r++) {
            int q = w * 4 + r;
            float v[4];
#pragma unroll
            for (int j = 0; j < 4; j++) v[j] = Ss[q][lane + 32 * j];
            float m = fmaxf(fmaxf(v[0], v[1]), fmaxf(v[2], v[3]));
#pragma unroll
            for (int off = 16; off > 0; off >>= 1)
                m = fmaxf(m, __shfl_xor_sync(0xffffffffu, m, off));
            float s = 0.f;
#pragma unroll
            for (int j = 0; j < 4; j++) s += expf(v[j] - m);
#pragma unroll
            for (int off = 16; off > 0; off >>= 1)
                s += __shfl_xor_sync(0xffffffffu, s, off);
            float inv = 1.f / s;
#pragma unroll
            for (int j = 0; j < 4; j++) Ss[q][lane + 32 * j] = expf(v[j] - m) * inv;
        }
    }
    for (int e = tid; e < 128 * 64; e += 128) {
        int s = e >> 6, d = e & 63;
        KVs[s][d] = g_V[(b * S_CURR + s) * D_MODEL + h * DH + d];
    }
    __syncthreads();

    {
        int d = tid & 63;
        int qb = tid >> 6;
#pragma unroll
        for (int qq = 0; qq < 8; qq++) {
            int q = qq * 2 + qb;
            float o = 0.f;
#pragma unroll 8
            for (int t = 0; t < 128; t++) o = fmaf(Ss[q][t], KVs[t][d], o);
            g_att[(b * 16 + q) * D_MODEL + h * DH + d] = o;
        }
    }
}

__global__ void tanh_kernel() {
    int e = blockIdx.x * blockDim.x + threadIdx.x;
    if (e < M_GATH * D_MODEL) g_att[e] = tanhf(g_att[e]);
}

// =======================================================================
// log-softmax
// =======================================================================
__global__ __launch_bounds__(256)
void lse_kernel(const float* __restrict__ out) {
    const int row = blockIdx.x;
    const float* x = out + (long long)row * N_CAND;
    float m = -INFINITY, s = 0.f;
    for (int c = threadIdx.x; c < N_CAND; c += 256) {
        float v = x[c];
        if (v <= m) {
            s += expf(v - m);
        } else {
            s = s * expf(m - v) + 1.f;
            m = v;
        }
    }
    __shared__ float sm_[256], ssum[256];
    sm_[threadIdx.x] = m;
    ssum[threadIdx.x] = s;
    __syncthreads();
    for (int stride = 128; stride > 0; stride >>= 1) {
        if (threadIdx.x < stride) {
            float m1 = sm_[threadIdx.x],          s1 = ssum[threadIdx.x];
            float m2 = sm_[threadIdx.x + stride], s2 = ssum[threadIdx.x + stride];
            float M = fmaxf(m1, m2);
            float S = s1 * expf(m1 - M) + s2 * expf(m2 - M);
            sm_[threadIdx.x] = M; ssum[threadIdx.x] = S;
        }
        __syncthreads();
    }
    if (threadIdx.x == 0) g_lse[row] = sm_[0] + logf(ssum[0]);
}

__global__ void sub_kernel(float* __restrict__ out) {
    int row = blockIdx.y;
    int c = blockIdx.x * blockDim.x + threadIdx.x;
    if (c < N_CAND) out[(long long)row * N_CAND + c] -= g_lse[row];
}

// =======================================================================
// launch
// =======================================================================
extern "C" void kernel_launch(void* const* d_in, const int* in_sizes, int n_in,
                              void* d_out, int out_size) {
    const int*   mask_pos  = (const int*)d_in[2];
    const int*   mask_curr = (const int*)d_in[3];
    const float* emb       = (const float*)d_in[5];
    const float* c_wq      = (const float*)d_in[12];
    const float* c_bq      = (const float*)d_in[13];
    const float* c_wk      = (const float*)d_in[14];
    const float* c_bk      = (const float*)d_in[15];
    const float* c_wv      = (const float*)d_in[16];
    const float* c_bv      = (const float*)d_in[17];
    const float* t2_w      = (const float*)d_in[24];
    const float* t2_b      = (const float*)d_in[25];
    float* out = (float*)d_out;

    float *p_curr, *p_qin, *p_K, *p_V, *p_Qm, *p_att, *p_hyb;
    cudaGetSymbolAddress((void**)&p_curr, g_curr);
    cudaGetSymbolAddress((void**)&p_qin,  g_qin);
    cudaGetSymbolAddress((void**)&p_K,    g_K);
    cudaGetSymbolAddress((void**)&p_V,    g_V);
    cudaGetSymbolAddress((void**)&p_Qm,   g_Qm);
    cudaGetSymbolAddress((void**)&p_att,  g_att);
    cudaGetSymbolAddress((void**)&p_hyb,  g_hyb);

    cudaFuncSetAttribute(gemm_mma_kernel,
                         cudaFuncAttributeMaxDynamicSharedMemorySize, GSMEM);

    // 1) embeddings + positional encodings
    build_curr_kernel<<<(BATCH * S_CURR * D_MODEL) / 256, 256>>>(mask_curr, emb);
    build_qin_kernel<<<(M_GATH * D_MODEL) / 256, 256>>>(mask_curr, mask_pos, emb);

    // 2) projections (HMMA, split bf16)
    gemm_mma_kernel<<<dim3(32, 4), 256, GSMEM>>>(p_curr, c_wk, c_bk, p_K,
                                                 D_MODEL, D_MODEL);
    gemm_mma_kernel<<<dim3(32, 4), 256, GSMEM>>>(p_curr, c_wv, c_bv, p_V,
                                                 D_MODEL, D_MODEL);
    gemm_mma_kernel<<<dim3(4, 4),  256, GSMEM>>>(p_qin, c_wq, c_bq, p_Qm,
                                                 D_MODEL, D_MODEL);

    // 3) attention
    attn_kernel<<<BATCH * HEADS, 128>>>();

    // 4) hyb = tanh(att) @ t2_w^T + t2_b
    tanh_kernel<<<(M_GATH * D_MODEL) / 256, 256>>>();
    gemm_mma_kernel<<<dim3(4, 4), 256, GSMEM>>>(p_att, t2_w, t2_b, p_hyb,
                                                D_MODEL, D_MODEL);

    // 5) scores = hyb @ emb[2:]^T  (m-tiles fastest -> 4 CTAs share B tile)
    gemm_mma_kernel<<<dim3(4, (N_CAND + 127) / 128), 256, GSMEM>>>(
        p_hyb, emb + 2 * D_MODEL, nullptr, out, N_CAND, N_CAND);

    // 6) log_softmax
    lse_kernel<<<M_GATH, 256>>>(out);
    {
        dim3 grid((N_CAND + 255) / 256, M_GATH);
        sub_kernel<<<grid, 256>>>(out);
    }
}

// round 12
// speedup vs baseline: 2.8763x; 1.0097x over previous
#include <cuda_runtime.h>
#include <cuda_bf16.h>
#include <math.h>
#include <stdint.h>

// ---------------- problem constants ----------------
#define D_MODEL   512
#define HEADS     8
#define DH        64
#define BATCH     32
#define S_CURR    128
#define N_MASK    16
#define N_CAND    39998
#define M_GATH    (BATCH * N_MASK)   // 512
#define NROWS_KV  (BATCH * S_CURR)   // 4096

// ---------------- scratch (static device memory) ----------------
__device__ __nv_bfloat16 g_currhi[NROWS_KV * D_MODEL];
__device__ __nv_bfloat16 g_currlo[NROWS_KV * D_MODEL];
__device__ __nv_bfloat16 g_qinhi [M_GATH * D_MODEL];
__device__ __nv_bfloat16 g_qinlo [M_GATH * D_MODEL];
__device__ __nv_bfloat16 g_wkhi[D_MODEL * D_MODEL], g_wklo[D_MODEL * D_MODEL];
__device__ __nv_bfloat16 g_wvhi[D_MODEL * D_MODEL], g_wvlo[D_MODEL * D_MODEL];
__device__ __nv_bfloat16 g_wqhi[D_MODEL * D_MODEL], g_wqlo[D_MODEL * D_MODEL];
__device__ __nv_bfloat16 g_twhi[D_MODEL * D_MODEL], g_twlo[D_MODEL * D_MODEL];
__device__ __nv_bfloat16 g_embhi[(size_t)N_CAND * D_MODEL];
__device__ __nv_bfloat16 g_emblo[(size_t)N_CAND * D_MODEL];
__device__ __nv_bfloat16 g_t2ahi[M_GATH * D_MODEL], g_t2alo[M_GATH * D_MODEL];
__device__ __nv_bfloat16 g_hybhi[M_GATH * D_MODEL], g_hyblo[M_GATH * D_MODEL];
__device__ float g_K  [NROWS_KV * D_MODEL];
__device__ float g_V  [NROWS_KV * D_MODEL];
__device__ float g_Qm [M_GATH * D_MODEL];
__device__ float g_att[M_GATH * D_MODEL];
__device__ float g_hyb[M_GATH * D_MODEL];
#define NT_SCORES 313                 // ceil(40064/128)
__device__ float g_pm[M_GATH * NT_SCORES];
__device__ float g_ps[M_GATH * NT_SCORES];
__device__ float g_lse[M_GATH];

// =======================================================================
// helpers
// =======================================================================
__device__ __forceinline__ uint32_t smem_u32(const void* p) {
    uint32_t a;
    asm("{ .reg .u64 t; cvta.to.shared.u64 t, %1; cvt.u32.u64 %0, t; }"
        : "=r"(a) : "l"(p));
    return a;
}

#define LDSM4(r0, r1, r2, r3, addr) \
    asm volatile("ldmatrix.sync.aligned.m8n8.x4.shared.b16 {%0,%1,%2,%3}, [%4];" \
                 : "=r"(r0), "=r"(r1), "=r"(r2), "=r"(r3) : "r"(addr))

#define MMA16816(d, a, b) \
    asm volatile("mma.sync.aligned.m16n8k16.row.col.f32.bf16.bf16.f32 " \
                 "{%0,%1,%2,%3}, {%4,%5,%6,%7}, {%8,%9}, {%0,%1,%2,%3};" \
                 : "+f"((d)[0]), "+f"((d)[1]), "+f"((d)[2]), "+f"((d)[3]) \
                 : "r"((a)[0]), "r"((a)[1]), "r"((a)[2]), "r"((a)[3]), \
                   "r"((b)[0]), "r"((b)[1]))

#define CP_ASYNC16(dst, src, sz) \
    asm volatile("cp.async.cg.shared.global [%0], [%1], 16, %2;" \
                 :: "r"(dst), "l"(src), "r"(sz))
#define CP_COMMIT() asm volatile("cp.async.commit_group;" ::: "memory")
#define CP_WAIT2()  asm volatile("cp.async.wait_group 2;" ::: "memory")

// safe logsumexp combine
__device__ __forceinline__ void lse_comb(float& m, float& s, float m2, float s2) {
    float M = fmaxf(m, m2);
    if (M == -INFINITY) { m = M; s = 0.f; return; }
    s = s * expf(m - M) + s2 * expf(m2 - M);
    m = M;
}

// split one float4 into packed bf16 hi/lo
__device__ __forceinline__ void split4(float4 v, uint2& h, uint2& l) {
    __nv_bfloat162 h01 = __floats2bfloat162_rn(v.x, v.y);
    __nv_bfloat162 h23 = __floats2bfloat162_rn(v.z, v.w);
    float lx = v.x - __bfloat162float(h01.x);
    float ly = v.y - __bfloat162float(h01.y);
    float lz = v.z - __bfloat162float(h23.x);
    float lw = v.w - __bfloat162float(h23.y);
    __nv_bfloat162 l01 = __floats2bfloat162_rn(lx, ly);
    __nv_bfloat162 l23 = __floats2bfloat162_rn(lz, lw);
    h = make_uint2(*reinterpret_cast<unsigned*>(&h01), *reinterpret_cast<unsigned*>(&h23));
    l = make_uint2(*reinterpret_cast<unsigned*>(&l01), *reinterpret_cast<unsigned*>(&l23));
}

// =======================================================================
// split kernels
// =======================================================================
__global__ void split_kernel(const float* __restrict__ src,
                             __nv_bfloat16* __restrict__ hi,
                             __nv_bfloat16* __restrict__ lo, int n4) {
    int i = blockIdx.x * blockDim.x + threadIdx.x;
    if (i >= n4) return;
    uint2 h, l;
    split4(((const float4*)src)[i], h, l);
    ((uint2*)hi)[i] = h;
    ((uint2*)lo)[i] = l;
}

__global__ void tanh_split_kernel(const float* __restrict__ src,
                                  __nv_bfloat16* __restrict__ hi,
                                  __nv_bfloat16* __restrict__ lo, int n4) {
    int i = blockIdx.x * blockDim.x + threadIdx.x;
    if (i >= n4) return;
    float4 v = ((const float4*)src)[i];
    v.x = tanhf(v.x); v.y = tanhf(v.y); v.z = tanhf(v.z); v.w = tanhf(v.w);
    uint2 h, l;
    split4(v, h, l);
    ((uint2*)hi)[i] = h;
    ((uint2*)lo)[i] = l;
}

// =======================================================================
// positional embedding + gathers (write bf16 hi/lo directly)
// =======================================================================
__device__ __forceinline__ float pe_val(int pos, int d) {
    const float c = -9.210340371976184f / (float)D_MODEL;  // -ln(10000)/512
    int i2 = d & ~1;
    float freq = expf((float)i2 * c);
    float arg = (float)pos * freq;
    return (d & 1) ? cosf(arg) : sinf(arg);
}

__global__ void build_curr_kernel(const int* __restrict__ idx,
                                  const float* __restrict__ emb) {
    int t = blockIdx.x * blockDim.x + threadIdx.x;     // one float4
    if (t >= NROWS_KV * D_MODEL / 4) return;
    int e  = t * 4;
    int d0 = e & (D_MODEL - 1);
    int row = e >> 9;
    int s  = row & (S_CURR - 1);
    int g  = idx[row];
    float4 v = *(const float4*)(emb + (size_t)g * D_MODEL + d0);
    v.x += pe_val(s, d0);     v.y += pe_val(s, d0 + 1);
    v.z += pe_val(s, d0 + 2); v.w += pe_val(s, d0 + 3);
    uint2 h, l;
    split4(v, h, l);
    ((uint2*)g_currhi)[t] = h;
    ((uint2*)g_currlo)[t] = l;
}

__global__ void build_qin_kernel(const int* __restrict__ idx,
                                 const int* __restrict__ mask_pos,
                                 const float* __restrict__ emb) {
    int t = blockIdx.x * blockDim.x + threadIdx.x;
    if (t >= M_GATH * D_MODEL / 4) return;
    int e  = t * 4;
    int d0 = e & (D_MODEL - 1);
    int r  = e >> 9;                  // b*16+i
    int b  = r >> 4;
    int s  = mask_pos[r];
    int g  = idx[b * S_CURR + s];
    float4 v = *(const float4*)(emb + (size_t)g * D_MODEL + d0);
    v.x += pe_val(s, d0);     v.y += pe_val(s, d0 + 1);
    v.z += pe_val(s, d0 + 2); v.w += pe_val(s, d0 + 3);
    uint2 h, l;
    split4(v, h, l);
    ((uint2*)g_qinhi)[t] = h;
    ((uint2*)g_qinlo)[t] = l;
}

// =======================================================================
// bf16 hi/lo HMMA GEMM, cp.async 4-stage pipeline.
// C[M,N] = A[M,512] * B[N,512]^T (+bias). 3-term hi/lo product.
// CTA tile 128x128, K-chunk 32, 256 threads (8 warps 4x2, warp 32x64).
// mode 1: also emit per-(row, CTA-tile) logsumexp partials (scores GEMM).
// =======================================================================
#define NCHUNK   16
#define LDT      40
#define LDTB     80
#define TILE_SZ  (128 * LDTB)        // 10240
#define OFF_AHI  0
#define OFF_ALO  (1 * TILE_SZ)
#define OFF_BHI  (2 * TILE_SZ)
#define OFF_BLO  (3 * TILE_SZ)
#define STAGE_SZ (4 * TILE_SZ)       // 40960
#define GSMEM    (4 * STAGE_SZ)      // 163840

__device__ __forceinline__ void issue_chunk(
    uint32_t stBase,
    const __nv_bfloat16* __restrict__ Ahi, const __nv_bfloat16* __restrict__ Alo,
    const __nv_bfloat16* __restrict__ Bhi, const __nv_bfloat16* __restrict__ Blo,
    int mBase, int nBase, int Nrows, int kt, int tid)
{
#pragma unroll
    for (int i = 0; i < 8; i++) {
        int idx  = tid + i * 256;
        int tile = idx >> 9;          // constant per i
        int w    = idx & 511;
        int row  = w >> 2;
        int c16  = w & 3;
        uint32_t dst = stBase + tile * TILE_SZ + row * LDTB + c16 * 16;
        const __nv_bfloat16* base =
            (tile == 0) ? Ahi : (tile == 1) ? Alo : (tile == 2) ? Bhi : Blo;
        int gr = (tile < 2) ? (mBase + row) : (nBase + row);
        int sz = 16;
        if (tile >= 2 && gr >= Nrows) { sz = 0; gr = 0; }
        const char* src = (const char*)base + (long long)gr * 1024 + kt * 64 + c16 * 16;
        CP_ASYNC16(dst, src, sz);
    }
}

__global__ __launch_bounds__(256, 1)
void gemm_bf16_kernel(const __nv_bfloat16* __restrict__ Ahi,
                      const __nv_bfloat16* __restrict__ Alo,
                      const __nv_bfloat16* __restrict__ Bhi,
                      const __nv_bfloat16* __restrict__ Blo,
                      const float* __restrict__ bias,
                      float* __restrict__ C,
                      int Nrows, int ldc, int mode,
                      float* __restrict__ pm, float* __restrict__ ps)
{
    extern __shared__ char sm[];
    const uint32_t smb = smem_u32(sm);
    const int tid  = threadIdx.x;
    const int lane = tid & 31;
    const int wid  = tid >> 5;
    const int mBase = blockIdx.x * 128;
    const int nBase = blockIdx.y * 128;
    const int mW = (wid & 3) * 32;
    const int nW = (wid >> 2) * 64;
    const uint32_t laneOff = (lane & 15) * LDTB + (lane >> 4) * 16;

    float acc[2][8][4];
#pragma unroll
    for (int mf = 0; mf < 2; mf++)
#pragma unroll
        for (int nf = 0; nf < 8; nf++)
#pragma unroll
            for (int j = 0; j < 4; j++) acc[mf][nf][j] = 0.f;

    // prologue: chunks 0..2 -> stages 0..2
#pragma unroll
    for (int c = 0; c < 3; c++) {
        issue_chunk(smb + c * STAGE_SZ, Ahi, Alo, Bhi, Blo,
                    mBase, nBase, Nrows, c, tid);
        CP_COMMIT();
    }

#pragma unroll 1
    for (int kt = 0; kt < NCHUNK; kt++) {
        CP_WAIT2();
        __syncthreads();
        if (kt + 3 < NCHUNK)
            issue_chunk(smb + ((kt + 3) & 3) * STAGE_SZ, Ahi, Alo, Bhi, Blo,
                        mBase, nBase, Nrows, kt + 3, tid);
        CP_COMMIT();   // empty groups near the end keep wait accounting uniform

        const uint32_t sOff = (kt & 3) * STAGE_SZ;
#pragma unroll
        for (int p = 0; p < 3; p++) {
            uint32_t aT = smb + sOff + (p == 2 ? OFF_ALO : OFF_AHI) + mW * LDTB + laneOff;
            uint32_t bT = smb + sOff + (p == 1 ? OFF_BLO : OFF_BHI) + nW * LDTB + laneOff;
#pragma unroll
            for (int ks = 0; ks < 2; ks++) {
                uint32_t a[2][4];
                LDSM4(a[0][0], a[0][1], a[0][2], a[0][3], aT + ks * 32);
                LDSM4(a[1][0], a[1][1], a[1][2], a[1][3], aT + 16 * LDTB + ks * 32);
                uint32_t b[8][2];
#pragma unroll
                for (int nq = 0; nq < 4; nq++) {
                    uint32_t r0, r1, r2, r3;
                    LDSM4(r0, r1, r2, r3, bT + nq * 16 * LDTB + ks * 32);
                    b[2 * nq][0] = r0;      b[2 * nq][1] = r2;
                    b[2 * nq + 1][0] = r1;  b[2 * nq + 1][1] = r3;
                }
#pragma unroll
                for (int mf = 0; mf < 2; mf++)
#pragma unroll
                    for (int nf = 0; nf < 8; nf++)
                        MMA16816(acc[mf][nf], a[mf], b[nf]);
            }
        }
    }

    // ---------------- epilogue: C write ----------------
    const int r0l = lane >> 2;
    const int c0l = (lane & 3) * 2;
#pragma unroll
    for (int mf = 0; mf < 2; mf++) {
#pragma unroll
        for (int nf = 0; nf < 8; nf++) {
            int row = mBase + mW + mf * 16 + r0l;
            int col = nBase + nW + nf * 8 + c0l;
            float* cp0 = C + (long long)row * ldc;
            float* cp1 = C + (long long)(row + 8) * ldc;
            if (col + 1 < Nrows) {
                float b0 = bias ? bias[col] : 0.f;
                float b1 = bias ? bias[col + 1] : 0.f;
                *(float2*)(cp0 + col) = make_float2(acc[mf][nf][0] + b0,
                                                    acc[mf][nf][1] + b1);
                *(float2*)(cp1 + col) = make_float2(acc[mf][nf][2] + b0,
                                                    acc[mf][nf][3] + b1);
            } else if (col < Nrows) {
                float b0 = bias ? bias[col] : 0.f;
                cp0[col] = acc[mf][nf][0] + b0;
                cp1[col] = acc[mf][nf][2] + b0;
            }
        }
    }

    // ---------------- epilogue: partial logsumexp (scores mode) ----------
    if (mode == 1) {
        float2* partSm = (float2*)sm;   // 2 x 128 float2 (stage-0 region, free)
        const int whalf = wid >> 2;
        const int wsub  = wid & 3;
#pragma unroll
        for (int mf = 0; mf < 2; mf++) {
#pragma unroll
            for (int h = 0; h < 2; h++) {
                float m = -INFINITY;
#pragma unroll
                for (int nf = 0; nf < 8; nf++)
#pragma unroll
                    for (int j = 0; j < 2; j++) {
                        int col = nBase + nW + nf * 8 + c0l + j;
                        if (col < Nrows) m = fmaxf(m, acc[mf][nf][h * 2 + j]);
                    }
                float s = 0.f;
#pragma unroll
                for (int nf = 0; nf < 8; nf++)
#pragma unroll
                    for (int j = 0; j < 2; j++) {
                        int col = nBase + nW + nf * 8 + c0l + j;
                        if (col < Nrows) s += expf(acc[mf][nf][h * 2 + j] - m);
                    }
#pragma unroll
                for (int o = 1; o <= 2; o <<= 1) {
                    float m2 = __shfl_xor_sync(0xffffffffu, m, o);
                    float s2 = __shfl_xor_sync(0xffffffffu, s, o);
                    lse_comb(m, s, m2, s2);
                }
                if ((lane & 3) == 0) {
                    int lr = wsub * 32 + mf * 16 + h * 8 + r0l;
                    partSm[whalf * 128 + lr] = make_float2(m, s);
                }
            }
        }
        __syncthreads();
        if (tid < 128) {
            float2 p0 = partSm[tid];
            float2 p1 = partSm[128 + tid];
            float m = p0.x, s = p0.y;
            lse_comb(m, s, p1.x, p1.y);
            int gi = (mBase + tid) * gridDim.y + blockIdx.y;
            pm[gi] = m;
            ps[gi] = s;
        }
    }
}

// =======================================================================
// attention (per b,h): Qm(16,64) x K(128,64) -> softmax -> x V
// =======================================================================
__global__ __launch_bounds__(128)
void attn_kernel() {
    const int b = blockIdx.x >> 3;
    const int h = blockIdx.x & 7;
    const int tid = threadIdx.x;

    __shared__ float Qs[16][64];
    __shared__ float KVs[128][65];
    __shared__ float Ss[16][128];

    for (int e = tid; e < 16 * 64; e += 128) {
        int q = e >> 6, d = e & 63;
        Qs[q][d] = g_Qm[(b * 16 + q) * D_MODEL + h * DH + d];
    }
    for (int e = tid; e < 128 * 64; e += 128) {
        int s = e >> 6, d = e & 63;
        KVs[s][d] = g_K[(b * S_CURR + s) * D_MODEL + h * DH + d];
    }
    __syncthreads();

    {
        float acc[16];
#pragma unroll
        for (int q = 0; q < 16; q++) acc[q] = 0.f;
#pragma unroll 8
        for (int d = 0; d < 64; d++) {
            float kv = KVs[tid][d];
#pragma unroll
            for (int q = 0; q < 16; q++) acc[q] = fmaf(Qs[q][d], kv, acc[q]);
        }
#pragma unroll
        for (int q = 0; q < 16; q++) Ss[q][tid] = acc[q];
    }
    __syncthreads();

    {
        int w = tid >> 5, lane = tid & 31;
        for (int r = 0; r < 4; r++) {
            int q = w * 4 + r;
            float v[4];
#pragma unroll
            for (int j = 0; j < 4; j++) v[j] = Ss[q][lane + 32 * j];
            float m = fmaxf(fmaxf(v[0], v[1]), fmaxf(v[2], v[3]));
#pragma unroll
            for (int off = 16; off > 0; off >>= 1)
                m = fmaxf(m, __shfl_xor_sync(0xffffffffu, m, off));
            float s = 0.f;
#pragma unroll
            for (int j = 0; j < 4; j++) s += expf(v[j] - m);
#pragma unroll
            for (int off = 16; off > 0; off >>= 1)
                s += __shfl_xor_sync(0xffffffffu, s, off);
            float inv = 1.f / s;
#pragma unroll
            for (int j = 0; j < 4; j++) Ss[q][lane + 32 * j] = expf(v[j] - m) * inv;
        }
    }
    for (int e = tid; e < 128 * 64; e += 128) {
        int s = e >> 6, d = e & 63;
        KVs[s][d] = g_V[(b * S_CURR + s) * D_MODEL + h * DH + d];
    }
    __syncthreads();

    {
        int d = tid & 63;
        int qb = tid >> 6;
#pragma unroll
        for (int qq = 0; qq < 8; qq++) {
            int q = qq * 2 + qb;
            float o = 0.f;
#pragma unroll 8
            for (int t = 0; t < 128; t++) o = fmaf(Ss[q][t], KVs[t][d], o);
            g_att[(b * 16 + q) * D_MODEL + h * DH + d] = o;
        }
    }
}

// =======================================================================
// lse reduce over tiles + subtract
// =======================================================================
__global__ __launch_bounds__(128)
void lse_reduce_kernel() {
    const int row = blockIdx.x;
    const int tid = threadIdx.x;
    float m = -INFINITY, s = 0.f;
    for (int t = tid; t < NT_SCORES; t += 128)
        lse_comb(m, s, g_pm[row * NT_SCORES + t], g_ps[row * NT_SCORES + t]);
    __shared__ float msh[128], ssh[128];
    msh[tid] = m; ssh[tid] = s;
    __syncthreads();
    for (int st = 64; st > 0; st >>= 1) {
        if (tid < st) {
            float mm = msh[tid], ss = ssh[tid];
            lse_comb(mm, ss, msh[tid + st], ssh[tid + st]);
            msh[tid] = mm; ssh[tid] = ss;
        }
        __syncthreads();
    }
    if (tid == 0) g_lse[row] = msh[0] + logf(ssh[0]);
}

__global__ void sub_kernel(float* __restrict__ out) {
    int row = blockIdx.y;
    int i = blockIdx.x * blockDim.x + threadIdx.x;   // float2 index
    if (i >= N_CAND / 2) return;
    float l = g_lse[row];
    float2* p = (float2*)(out + (long long)row * N_CAND) + i;
    float2 v = *p;
    v.x -= l; v.y -= l;
    *p = v;
}

// =======================================================================
// launch
// =======================================================================
extern "C" void kernel_launch(void* const* d_in, const int* in_sizes, int n_in,
                              void* d_out, int out_size) {
    const int*   mask_pos  = (const int*)d_in[2];
    const int*   mask_curr = (const int*)d_in[3];
    const float* emb       = (const float*)d_in[5];
    const float* c_wq      = (const float*)d_in[12];
    const float* c_bq      = (const float*)d_in[13];
    const float* c_wk      = (const float*)d_in[14];
    const float* c_bk      = (const float*)d_in[15];
    const float* c_wv      = (const float*)d_in[16];
    const float* c_bv      = (const float*)d_in[17];
    const float* t2_w      = (const float*)d_in[24];
    const float* t2_b      = (const float*)d_in[25];
    float* out = (float*)d_out;

    // symbol addresses
    __nv_bfloat16 *currhi, *currlo, *qinhi, *qinlo;
    __nv_bfloat16 *wkhi, *wklo, *wvhi, *wvlo, *wqhi, *wqlo, *twhi, *twlo;
    __nv_bfloat16 *embhi, *emblo, *t2ahi, *t2alo, *hybhi, *hyblo;
    float *pK, *pV, *pQm, *pAtt, *pHyb, *pPm, *pPs;
    cudaGetSymbolAddress((void**)&currhi, g_currhi);
    cudaGetSymbolAddress((void**)&currlo, g_currlo);
    cudaGetSymbolAddress((void**)&qinhi,  g_qinhi);
    cudaGetSymbolAddress((void**)&qinlo,  g_qinlo);
    cudaGetSymbolAddress((void**)&wkhi, g_wkhi); cudaGetSymbolAddress((void**)&wklo, g_wklo);
    cudaGetSymbolAddress((void**)&wvhi, g_wvhi); cudaGetSymbolAddress((void**)&wvlo, g_wvlo);
    cudaGetSymbolAddress((void**)&wqhi, g_wqhi); cudaGetSymbolAddress((void**)&wqlo, g_wqlo);
    cudaGetSymbolAddress((void**)&twhi, g_twhi); cudaGetSymbolAddress((void**)&twlo, g_twlo);
    cudaGetSymbolAddress((void**)&embhi, g_embhi);
    cudaGetSymbolAddress((void**)&emblo, g_emblo);
    cudaGetSymbolAddress((void**)&t2ahi, g_t2ahi);
    cudaGetSymbolAddress((void**)&t2alo, g_t2alo);
    cudaGetSymbolAddress((void**)&hybhi, g_hybhi);
    cudaGetSymbolAddress((void**)&hyblo, g_hyblo);
    cudaGetSymbolAddress((void**)&pK,   g_K);
    cudaGetSymbolAddress((void**)&pV,   g_V);
    cudaGetSymbolAddress((void**)&pQm,  g_Qm);
    cudaGetSymbolAddress((void**)&pAtt, g_att);
    cudaGetSymbolAddress((void**)&pHyb, g_hyb);
    cudaGetSymbolAddress((void**)&pPm,  g_pm);
    cudaGetSymbolAddress((void**)&pPs,  g_ps);

    cudaFuncSetAttribute(gemm_bf16_kernel,
                         cudaFuncAttributeMaxDynamicSharedMemorySize, GSMEM);

    const int W4 = D_MODEL * D_MODEL / 4;   // 65536

    // 0) pre-split static operands
    split_kernel<<<(N_CAND * 128 + 255) / 256, 256>>>(emb + 2 * D_MODEL, embhi, emblo,
                                                      N_CAND * 128);
    split_kernel<<<W4 / 256, 256>>>(c_wk, wkhi, wklo, W4);
    split_kernel<<<W4 / 256, 256>>>(c_wv, wvhi, wvlo, W4);
    split_kernel<<<W4 / 256, 256>>>(c_wq, wqhi, wqlo, W4);
    split_kernel<<<W4 / 256, 256>>>(t2_w, twhi, twlo, W4);

    // 1) embeddings + positional encodings (direct hi/lo)
    build_curr_kernel<<<(NROWS_KV * D_MODEL / 4) / 256, 256>>>(mask_curr, emb);
    build_qin_kernel<<<(M_GATH * D_MODEL / 4) / 256, 256>>>(mask_curr, mask_pos, emb);

    // 2) projections
    gemm_bf16_kernel<<<dim3(32, 4), 256, GSMEM>>>(currhi, currlo, wkhi, wklo,
                                                  c_bk, pK, D_MODEL, D_MODEL, 0,
                                                  nullptr, nullptr);
    gemm_bf16_kernel<<<dim3(32, 4), 256, GSMEM>>>(currhi, currlo, wvhi, wvlo,
                                                  c_bv, pV, D_MODEL, D_MODEL, 0,
                                                  nullptr, nullptr);
    gemm_bf16_kernel<<<dim3(4, 4), 256, GSMEM>>>(qinhi, qinlo, wqhi, wqlo,
                                                 c_bq, pQm, D_MODEL, D_MODEL, 0,
                                                 nullptr, nullptr);

    // 3) attention
    attn_kernel<<<BATCH * HEADS, 128>>>();

    // 4) hyb = tanh(att) @ t2_w^T + t2_b
    tanh_split_kernel<<<W4 / 256, 256>>>(pAtt, t2ahi, t2alo, W4);
    gemm_bf16_kernel<<<dim3(4, 4), 256, GSMEM>>>(t2ahi, t2alo, twhi, twlo,
                                                 t2_b, pHyb, D_MODEL, D_MODEL, 0,
                                                 nullptr, nullptr);
    split_kernel<<<W4 / 256, 256>>>(pHyb, hybhi, hyblo, W4);

    // 5) scores + fused partial logsumexp
    gemm_bf16_kernel<<<dim3(4, NT_SCORES), 256, GSMEM>>>(
        hybhi, hyblo, embhi, emblo, nullptr, out, N_CAND, N_CAND, 1, pPm, pPs);

    // 6) finish log_softmax
    lse_reduce_kernel<<<M_GATH, 128>>>();
    {
        dim3 grid((N_CAND / 2 + 255) / 256, M_GATH);
        sub_kernel<<<grid, 256>>>(out);
    }
}

// round 15
// speedup vs baseline: 3.0178x; 1.0492x over previous
#include <cuda_runtime.h>
#include <cuda_bf16.h>
#include <math.h>
#include <stdint.h>

// ---------------- problem constants ----------------
#define D_MODEL   512
#define HEADS     8
#define DH        64
#define BATCH     32
#define S_CURR    128
#define N_MASK    16
#define N_CAND    39998
#define M_GATH    (BATCH * N_MASK)   // 512
#define NROWS_KV  (BATCH * S_CURR)   // 4096

// ---------------- scratch (static device memory) ----------------
__device__ __nv_bfloat16 g_currhi[NROWS_KV * D_MODEL];
__device__ __nv_bfloat16 g_currlo[NROWS_KV * D_MODEL];
__device__ __nv_bfloat16 g_qinhi [M_GATH * D_MODEL];
__device__ __nv_bfloat16 g_qinlo [M_GATH * D_MODEL];
__device__ __nv_bfloat16 g_wkhi[D_MODEL * D_MODEL], g_wklo[D_MODEL * D_MODEL];
__device__ __nv_bfloat16 g_wvhi[D_MODEL * D_MODEL], g_wvlo[D_MODEL * D_MODEL];
__device__ __nv_bfloat16 g_wqhi[D_MODEL * D_MODEL], g_wqlo[D_MODEL * D_MODEL];
__device__ __nv_bfloat16 g_twhi[D_MODEL * D_MODEL], g_twlo[D_MODEL * D_MODEL];
__device__ __nv_bfloat16 g_embhi[(size_t)N_CAND * D_MODEL];
__device__ __nv_bfloat16 g_emblo[(size_t)N_CAND * D_MODEL];
__device__ __nv_bfloat16 g_t2ahi[M_GATH * D_MODEL], g_t2alo[M_GATH * D_MODEL];
__device__ __nv_bfloat16 g_hybhi[M_GATH * D_MODEL], g_hyblo[M_GATH * D_MODEL];
__device__ float g_K  [NROWS_KV * D_MODEL];
__device__ float g_V  [NROWS_KV * D_MODEL];
__device__ float g_Qm [M_GATH * D_MODEL];
__device__ float g_att[M_GATH * D_MODEL];
__device__ float g_hyb[M_GATH * D_MODEL];
#define NT_SCORES 313                 // ceil(40064/128)
__device__ float g_pm[M_GATH * NT_SCORES];
__device__ float g_ps[M_GATH * NT_SCORES];
__device__ float g_lse[M_GATH];

// =======================================================================
// helpers
// =======================================================================
__device__ __forceinline__ uint32_t smem_u32(const void* p) {
    uint32_t a;
    asm("{ .reg .u64 t; cvta.to.shared.u64 t, %1; cvt.u32.u64 %0, t; }"
        : "=r"(a) : "l"(p));
    return a;
}

#define LDSM4(r0, r1, r2, r3, addr) \
    asm volatile("ldmatrix.sync.aligned.m8n8.x4.shared.b16 {%0,%1,%2,%3}, [%4];" \
                 : "=r"(r0), "=r"(r1), "=r"(r2), "=r"(r3) : "r"(addr))

#define MMA16816(d, a, b) \
    asm volatile("mma.sync.aligned.m16n8k16.row.col.f32.bf16.bf16.f32 " \
                 "{%0,%1,%2,%3}, {%4,%5,%6,%7}, {%8,%9}, {%0,%1,%2,%3};" \
                 : "+f"((d)[0]), "+f"((d)[1]), "+f"((d)[2]), "+f"((d)[3]) \
                 : "r"((a)[0]), "r"((a)[1]), "r"((a)[2]), "r"((a)[3]), \
                   "r"((b)[0]), "r"((b)[1]))

#define CP_ASYNC16(dst, src, sz) \
    asm volatile("cp.async.cg.shared.global [%0], [%1], 16, %2;" \
                 :: "r"(dst), "l"(src), "r"(sz))
#define CP_COMMIT() asm volatile("cp.async.commit_group;" ::: "memory")
#define CP_WAIT2()  asm volatile("cp.async.wait_group 2;" ::: "memory")

// safe logsumexp combine
__device__ __forceinline__ void lse_comb(float& m, float& s, float m2, float s2) {
    float M = fmaxf(m, m2);
    if (M == -INFINITY) { m = M; s = 0.f; return; }
    s = s * expf(m - M) + s2 * expf(m2 - M);
    m = M;
}

// split one float4 into packed bf16 hi/lo
__device__ __forceinline__ void split4(float4 v, uint2& h, uint2& l) {
    __nv_bfloat162 h01 = __floats2bfloat162_rn(v.x, v.y);
    __nv_bfloat162 h23 = __floats2bfloat162_rn(v.z, v.w);
    float lx = v.x - __bfloat162float(h01.x);
    float ly = v.y - __bfloat162float(h01.y);
    float lz = v.z - __bfloat162float(h23.x);
    float lw = v.w - __bfloat162float(h23.y);
    __nv_bfloat162 l01 = __floats2bfloat162_rn(lx, ly);
    __nv_bfloat162 l23 = __floats2bfloat162_rn(lz, lw);
    h = make_uint2(*reinterpret_cast<unsigned*>(&h01), *reinterpret_cast<unsigned*>(&h23));
    l = make_uint2(*reinterpret_cast<unsigned*>(&l01), *reinterpret_cast<unsigned*>(&l23));
}

// =======================================================================
// split kernels
// =======================================================================
__global__ void split_kernel(const float* __restrict__ src,
                             __nv_bfloat16* __restrict__ hi,
                             __nv_bfloat16* __restrict__ lo, int n4) {
    int i = blockIdx.x * blockDim.x + threadIdx.x;
    if (i >= n4) return;
    uint2 h, l;
    split4(((const float4*)src)[i], h, l);
    ((uint2*)hi)[i] = h;
    ((uint2*)lo)[i] = l;
}

__global__ void tanh_split_kernel(const float* __restrict__ src,
                                  __nv_bfloat16* __restrict__ hi,
                                  __nv_bfloat16* __restrict__ lo, int n4) {
    int i = blockIdx.x * blockDim.x + threadIdx.x;
    if (i >= n4) return;
    float4 v = ((const float4*)src)[i];
    v.x = tanhf(v.x); v.y = tanhf(v.y); v.z = tanhf(v.z); v.w = tanhf(v.w);
    uint2 h, l;
    split4(v, h, l);
    ((uint2*)hi)[i] = h;
    ((uint2*)lo)[i] = l;
}

// =======================================================================
// positional embedding + gathers (write bf16 hi/lo directly)
// =======================================================================
__device__ __forceinline__ float pe_val(int pos, int d) {
    const float c = -9.210340371976184f / (float)D_MODEL;  // -ln(10000)/512
    int i2 = d & ~1;
    float freq = expf((float)i2 * c);
    float arg = (float)pos * freq;
    return (d & 1) ? cosf(arg) : sinf(arg);
}

__global__ void build_curr_kernel(const int* __restrict__ idx,
                                  const float* __restrict__ emb) {
    int t = blockIdx.x * blockDim.x + threadIdx.x;     // one float4
    if (t >= NROWS_KV * D_MODEL / 4) return;
    int e  = t * 4;
    int d0 = e & (D_MODEL - 1);
    int row = e >> 9;
    int s  = row & (S_CURR - 1);
    int g  = idx[row];
    float4 v = *(const float4*)(emb + (size_t)g * D_MODEL + d0);
    v.x += pe_val(s, d0);     v.y += pe_val(s, d0 + 1);
    v.z += pe_val(s, d0 + 2); v.w += pe_val(s, d0 + 3);
    uint2 h, l;
    split4(v, h, l);
    ((uint2*)g_currhi)[t] = h;
    ((uint2*)g_currlo)[t] = l;
}

__global__ void build_qin_kernel(const int* __restrict__ idx,
                                 const int* __restrict__ mask_pos,
                                 const float* __restrict__ emb) {
    int t = blockIdx.x * blockDim.x + threadIdx.x;
    if (t >= M_GATH * D_MODEL / 4) return;
    int e  = t * 4;
    int d0 = e & (D_MODEL - 1);
    int r  = e >> 9;                  // b*16+i
    int b  = r >> 4;
    int s  = mask_pos[r];
    int g  = idx[b * S_CURR + s];
    float4 v = *(const float4*)(emb + (size_t)g * D_MODEL + d0);
    v.x += pe_val(s, d0);     v.y += pe_val(s, d0 + 1);
    v.z += pe_val(s, d0 + 2); v.w += pe_val(s, d0 + 3);
    uint2 h, l;
    split4(v, h, l);
    ((uint2*)g_qinhi)[t] = h;
    ((uint2*)g_qinlo)[t] = l;
}

// =======================================================================
// bf16 hi/lo HMMA GEMM, cp.async 4-stage pipeline, 512 threads.
// C[M,N] = A[M,512] * B[N,512]^T (+bias). 3-term hi/lo product.
// CTA tile 128x128, K-chunk 32; 16 warps in 4x4, warp tile 32x32.
// Register double-buffered ldmatrix fragments across the 6 (pass,k16) steps.
// mode 1: also emit per-(row, CTA-tile) logsumexp partials (scores GEMM).
// =======================================================================
#define NCHUNK   16
#define LDTB     80
#define TILE_SZ  (128 * LDTB)        // 10240
#define OFF_AHI  0u
#define OFF_ALO  (1u * TILE_SZ)
#define OFF_BHI  (2u * TILE_SZ)
#define OFF_BLO  (3u * TILE_SZ)
#define STAGE_SZ (4u * TILE_SZ)      // 40960
#define GSMEM    (4 * 40960)         // 163840

__device__ __forceinline__ void issue_chunk(
    uint32_t stBase,
    const __nv_bfloat16* __restrict__ Ahi, const __nv_bfloat16* __restrict__ Alo,
    const __nv_bfloat16* __restrict__ Bhi, const __nv_bfloat16* __restrict__ Blo,
    int mBase, int nBase, int Nrows, int kt, int tid)
{
#pragma unroll
    for (int i = 0; i < 4; i++) {
        int idx  = tid + i * 512;     // 0..2047
        int tile = idx >> 9;          // constant per i
        int w    = idx & 511;
        int row  = w >> 2;
        int c16  = w & 3;
        uint32_t dst = stBase + tile * TILE_SZ + row * LDTB + c16 * 16;
        const __nv_bfloat16* base =
            (tile == 0) ? Ahi : (tile == 1) ? Alo : (tile == 2) ? Bhi : Blo;
        int gr = (tile < 2) ? (mBase + row) : (nBase + row);
        int sz = 16;
        if (tile >= 2 && gr >= Nrows) { sz = 0; gr = 0; }
        const char* src = (const char*)base + (long long)gr * 1024 + kt * 64 + c16 * 16;
        CP_ASYNC16(dst, src, sz);
    }
}

// fragment load for step s into buffer buf
#define LOADF(s, buf) do {                                                   \
    uint32_t aT = smb + sOff + AO[s] + mW * LDTB + laneOff + KO[s];          \
    LDSM4(a2[buf][0][0], a2[buf][0][1], a2[buf][0][2], a2[buf][0][3], aT);   \
    LDSM4(a2[buf][1][0], a2[buf][1][1], a2[buf][1][2], a2[buf][1][3],       \
          aT + 16 * LDTB);                                                   \
    uint32_t bT = smb + sOff + BO[s] + nW * LDTB + laneOff + KO[s];          \
    uint32_t r0_, r1_, r2_, r3_;                                             \
    LDSM4(r0_, r1_, r2_, r3_, bT);                                           \
    b2[buf][0][0] = r0_; b2[buf][0][1] = r2_;                                \
    b2[buf][1][0] = r1_; b2[buf][1][1] = r3_;                                \
    LDSM4(r0_, r1_, r2_, r3_, bT + 16 * LDTB);                               \
    b2[buf][2][0] = r0_; b2[buf][2][1] = r2_;                                \
    b2[buf][3][0] = r1_; b2[buf][3][1] = r3_;                                \
} while (0)

__global__ __launch_bounds__(512, 1)
void gemm_bf16_kernel(const __nv_bfloat16* __restrict__ Ahi,
                      const __nv_bfloat16* __restrict__ Alo,
                      const __nv_bfloat16* __restrict__ Bhi,
                      const __nv_bfloat16* __restrict__ Blo,
                      const float* __restrict__ bias,
                      float* __restrict__ C,
                      int Nrows, int ldc, int mode,
                      float* __restrict__ pm, float* __restrict__ ps)
{
    extern __shared__ char sm[];
    const uint32_t smb = smem_u32(sm);
    const int tid  = threadIdx.x;
    const int lane = tid & 31;
    const int wid  = tid >> 5;
    const int mBase = blockIdx.x * 128;
    const int nBase = blockIdx.y * 128;
    const int mW = (wid & 3) * 32;      // warp m offset
    const int nW = (wid >> 2) * 32;     // warp n offset
    const uint32_t laneOff = (lane & 15) * LDTB + (lane >> 4) * 16;

    float acc[2][4][4];
#pragma unroll
    for (int mf = 0; mf < 2; mf++)
#pragma unroll
        for (int nf = 0; nf < 4; nf++)
#pragma unroll
            for (int j = 0; j < 4; j++) acc[mf][nf][j] = 0.f;

    // prologue: chunks 0..2 -> stages 0..2
#pragma unroll
    for (int c = 0; c < 3; c++) {
        issue_chunk(smb + c * STAGE_SZ, Ahi, Alo, Bhi, Blo,
                    mBase, nBase, Nrows, c, tid);
        CP_COMMIT();
    }

    // step tables: (pass, k16) = (0,0)(0,1)(1,0)(1,1)(2,0)(2,1)
    const uint32_t AO[6] = {OFF_AHI, OFF_AHI, OFF_AHI, OFF_AHI, OFF_ALO, OFF_ALO};
    const uint32_t BO[6] = {OFF_BHI, OFF_BHI, OFF_BLO, OFF_BLO, OFF_BHI, OFF_BHI};
    const uint32_t KO[6] = {0, 32, 0, 32, 0, 32};

#pragma unroll 1
    for (int kt = 0; kt < NCHUNK; kt++) {
        CP_WAIT2();
        __syncthreads();
        if (kt + 3 < NCHUNK)
            issue_chunk(smb + ((kt + 3) & 3) * STAGE_SZ, Ahi, Alo, Bhi, Blo,
                        mBase, nBase, Nrows, kt + 3, tid);
        CP_COMMIT();   // empty groups keep wait accounting uniform

        const uint32_t sOff = (kt & 3) * STAGE_SZ;
        uint32_t a2[2][2][4];
        uint32_t b2[2][4][2];
        LOADF(0, 0);
#pragma unroll
        for (int s = 0; s < 6; s++) {
            const int cur = s & 1;
            if (s < 5) LOADF(s + 1, cur ^ 1);
#pragma unroll
            for (int mf = 0; mf < 2; mf++)
#pragma unroll
                for (int nf = 0; nf < 4; nf++)
                    MMA16816(acc[mf][nf], a2[cur][mf], b2[cur][nf]);
        }
    }

    // ---------------- epilogue: C write ----------------
    const int r0l = lane >> 2;
    const int c0l = (lane & 3) * 2;
#pragma unroll
    for (int mf = 0; mf < 2; mf++) {
#pragma unroll
        for (int nf = 0; nf < 4; nf++) {
            int row = mBase + mW + mf * 16 + r0l;
            int col = nBase + nW + nf * 8 + c0l;
            float* cp0 = C + (long long)row * ldc;
            float* cp1 = C + (long long)(row + 8) * ldc;
            if (col + 1 < Nrows) {
                float b0 = bias ? bias[col] : 0.f;
                float b1 = bias ? bias[col + 1] : 0.f;
                *(float2*)(cp0 + col) = make_float2(acc[mf][nf][0] + b0,
                                                    acc[mf][nf][1] + b1);
                *(float2*)(cp1 + col) = make_float2(acc[mf][nf][2] + b0,
                                                    acc[mf][nf][3] + b1);
            } else if (col < Nrows) {
                float b0 = bias ? bias[col] : 0.f;
                cp0[col] = acc[mf][nf][0] + b0;
                cp1[col] = acc[mf][nf][2] + b0;
            }
        }
    }

    // ---------------- epilogue: partial logsumexp (scores mode) ----------
    if (mode == 1) {
        __syncthreads();                     // all warps done with stage smem
        float2* partSm = (float2*)sm;        // 4 x 128 float2 = 4 KB
        const int wm = wid & 3;
        const int wn = wid >> 2;
#pragma unroll
        for (int mf = 0; mf < 2; mf++) {
#pragma unroll
            for (int h = 0; h < 2; h++) {
                float m = -INFINITY;
#pragma unroll
                for (int nf = 0; nf < 4; nf++)
#pragma unroll
                    for (int j = 0; j < 2; j++) {
                        int col = nBase + nW + nf * 8 + c0l + j;
                        if (col < Nrows) m = fmaxf(m, acc[mf][nf][h * 2 + j]);
                    }
                float s = 0.f;
#pragma unroll
                for (int nf = 0; nf < 4; nf++)
#pragma unroll
                    for (int j = 0; j < 2; j++) {
                        int col = nBase + nW + nf * 8 + c0l + j;
                        if (col < Nrows) s += expf(acc[mf][nf][h * 2 + j] - m);
                    }
#pragma unroll
                for (int o = 1; o <= 2; o <<= 1) {
                    float m2 = __shfl_xor_sync(0xffffffffu, m, o);
                    float s2 = __shfl_xor_sync(0xffffffffu, s, o);
                    lse_comb(m, s, m2, s2);
                }
                if ((lane & 3) == 0) {
                    int lr = wm * 32 + mf * 16 + h * 8 + r0l;
                    partSm[wn * 128 + lr] = make_float2(m, s);
                }
            }
        }
        __syncthreads();
        if (tid < 128) {
            float m = -INFINITY, s = 0.f;
#pragma unroll
            for (int wn2 = 0; wn2 < 4; wn2++) {
                float2 p = partSm[wn2 * 128 + tid];
                lse_comb(m, s, p.x, p.y);
            }
            int gi = (mBase + tid) * gridDim.y + blockIdx.y;
            pm[gi] = m;
            ps[gi] = s;
        }
    }
}

// =======================================================================
// attention (per b,h): Qm(16,64) x K(128,64) -> softmax -> x V
// =======================================================================
__global__ __launch_bounds__(128)
void attn_kernel() {
    const int b = blockIdx.x >> 3;
    const int h = blockIdx.x & 7;
    const int tid = threadIdx.x;

    __shared__ float Qs[16][64];
    __shared__ float KVs[128][65];
    __shared__ float Ss[16][128];

    for (int e = tid; e < 16 * 64; e += 128) {
        int q = e >> 6, d = e & 63;
        Qs[q][d] = g_Qm[(b * 16 + q) * D_MODEL + h * DH + d];
    }
    for (int e = tid; e < 128 * 64; e += 128) {
        int s = e >> 6, d = e & 63;
        KVs[s][d] = g_K[(b * S_CURR + s) * D_MODEL + h * DH + d];
    }
    __syncthreads();

    {
        float acc[16];
#pragma unroll
        for (int q = 0; q < 16; q++) acc[q] = 0.f;
#pragma unroll 8
        for (int d = 0; d < 64; d++) {
            float kv = KVs[tid][d];
#pragma unroll
            for (int q = 0; q < 16; q++) acc[q] = fmaf(Qs[q][d], kv, acc[q]);
        }
#pragma unroll
        for (int q = 0; q < 16; q++) Ss[q][tid] = acc[q];
    }
    __syncthreads();

    {
        int w = tid >> 5, lane = tid & 31;
        for (int r = 0; r < 4; r++) {
            int q = w * 4 + r;
            float v[4];
#pragma unroll
            for (int j = 0; j < 4; j++) v[j] = Ss[q][lane + 32 * j];
            float m = fmaxf(fmaxf(v[0], v[1]), fmaxf(v[2], v[3]));
#pragma unroll
            for (int off = 16; off > 0; off >>= 1)
                m = fmaxf(m, __shfl_xor_sync(0xffffffffu, m, off));
            float s = 0.f;
#pragma unroll
            for (int j = 0; j < 4; j++) s += expf(v[j] - m);
#pragma unroll
            for (int off = 16; off > 0; off >>= 1)
                s += __shfl_xor_sync(0xffffffffu, s, off);
            float inv = 1.f / s;
#pragma unroll
            for (int j = 0; j < 4; j++) Ss[q][lane + 32 * j] = expf(v[j] - m) * inv;
        }
    }
    for (int e = tid; e < 128 * 64; e += 128) {
        int s = e >> 6, d = e & 63;
        KVs[s][d] = g_V[(b * S_CURR + s) * D_MODEL + h * DH + d];
    }
    __syncthreads();

    {
        int d = tid & 63;
        int qb = tid >> 6;
#pragma unroll
        for (int qq = 0; qq < 8; qq++) {
            int q = qq * 2 + qb;
            float o = 0.f;
#pragma unroll 8
            for (int t = 0; t < 128; t++) o = fmaf(Ss[q][t], KVs[t][d], o);
            g_att[(b * 16 + q) * D_MODEL + h * DH + d] = o;
        }
    }
}

// =======================================================================
// lse reduce over tiles + subtract
// =======================================================================
__global__ __launch_bounds__(128)
void lse_reduce_kernel() {
    const int row = blockIdx.x;
    const int tid = threadIdx.x;
    float m = -INFINITY, s = 0.f;
    for (int t = tid; t < NT_SCORES; t += 128)
        lse_comb(m, s, g_pm[row * NT_SCORES + t], g_ps[row * NT_SCORES + t]);
    __shared__ float msh[128], ssh[128];
    msh[tid] = m; ssh[tid] = s;
    __syncthreads();
    for (int st = 64; st > 0; st >>= 1) {
        if (tid < st) {
            float mm = msh[tid], ss = ssh[tid];
            lse_comb(mm, ss, msh[tid + st], ssh[tid + st]);
            msh[tid] = mm; ssh[tid] = ss;
        }
        __syncthreads();
    }
    if (tid == 0) g_lse[row] = msh[0] + logf(ssh[0]);
}

__global__ void sub_kernel(float* __restrict__ out) {
    int row = blockIdx.y;
    int i = blockIdx.x * blockDim.x + threadIdx.x;   // float2 index
    if (i >= N_CAND / 2) return;
    float l = g_lse[row];
    float2* p = (float2*)(out + (long long)row * N_CAND) + i;
    float2 v = *p;
    v.x -= l; v.y -= l;
    *p = v;
}

// =======================================================================
// launch
// =======================================================================
extern "C" void kernel_launch(void* const* d_in, const int* in_sizes, int n_in,
                              void* d_out, int out_size) {
    const int*   mask_pos  = (const int*)d_in[2];
    const int*   mask_curr = (const int*)d_in[3];
    const float* emb       = (const float*)d_in[5];
    const float* c_wq      = (const float*)d_in[12];
    const float* c_bq      = (const float*)d_in[13];
    const float* c_wk      = (const float*)d_in[14];
    const float* c_bk      = (const float*)d_in[15];
    const float* c_wv      = (const float*)d_in[16];
    const float* c_bv      = (const float*)d_in[17];
    const float* t2_w      = (const float*)d_in[24];
    const float* t2_b      = (const float*)d_in[25];
    float* out = (float*)d_out;

    __nv_bfloat16 *currhi, *currlo, *qinhi, *qinlo;
    __nv_bfloat16 *wkhi, *wklo, *wvhi, *wvlo, *wqhi, *wqlo, *twhi, *twlo;
    __nv_bfloat16 *embhi, *emblo, *t2ahi, *t2alo, *hybhi, *hyblo;
    float *pK, *pV, *pQm, *pAtt, *pHyb, *pPm, *pPs;
    cudaGetSymbolAddress((void**)&currhi, g_currhi);
    cudaGetSymbolAddress((void**)&currlo, g_currlo);
    cudaGetSymbolAddress((void**)&qinhi,  g_qinhi);
    cudaGetSymbolAddress((void**)&qinlo,  g_qinlo);
    cudaGetSymbolAddress((void**)&wkhi, g_wkhi); cudaGetSymbolAddress((void**)&wklo, g_wklo);
    cudaGetSymbolAddress((void**)&wvhi, g_wvhi); cudaGetSymbolAddress((void**)&wvlo, g_wvlo);
    cudaGetSymbolAddress((void**)&wqhi, g_wqhi); cudaGetSymbolAddress((void**)&wqlo, g_wqlo);
    cudaGetSymbolAddress((void**)&twhi, g_twhi); cudaGetSymbolAddress((void**)&twlo, g_twlo);
    cudaGetSymbolAddress((void**)&embhi, g_embhi);
    cudaGetSymbolAddress((void**)&emblo, g_emblo);
    cudaGetSymbolAddress((void**)&t2ahi, g_t2ahi);
    cudaGetSymbolAddress((void**)&t2alo, g_t2alo);
    cudaGetSymbolAddress((void**)&hybhi, g_hybhi);
    cudaGetSymbolAddress((void**)&hyblo, g_hyblo);
    cudaGetSymbolAddress((void**)&pK,   g_K);
    cudaGetSymbolAddress((void**)&pV,   g_V);
    cudaGetSymbolAddress((void**)&pQm,  g_Qm);
    cudaGetSymbolAddress((void**)&pAtt, g_att);
    cudaGetSymbolAddress((void**)&pHyb, g_hyb);
    cudaGetSymbolAddress((void**)&pPm,  g_pm);
    cudaGetSymbolAddress((void**)&pPs,  g_ps);

    cudaFuncSetAttribute(gemm_bf16_kernel,
                         cudaFuncAttributeMaxDynamicSharedMemorySize, GSMEM);

    const int W4 = D_MODEL * D_MODEL / 4;   // 65536

    // 0) pre-split static operands
    split_kernel<<<(N_CAND * 128 + 255) / 256, 256>>>(emb + 2 * D_MODEL, embhi, emblo,
                                                      N_CAND * 128);
    split_kernel<<<W4 / 256, 256>>>(c_wk, wkhi, wklo, W4);
    split_kernel<<<W4 / 256, 256>>>(c_wv, wvhi, wvlo, W4);
    split_kernel<<<W4 / 256, 256>>>(c_wq, wqhi, wqlo, W4);
    split_kernel<<<W4 / 256, 256>>>(t2_w, twhi, twlo, W4);

    // 1) embeddings + positional encodings (direct hi/lo)
    build_curr_kernel<<<(NROWS_KV * D_MODEL / 4) / 256, 256>>>(mask_curr, emb);
    build_qin_kernel<<<(M_GATH * D_MODEL / 4) / 256, 256>>>(mask_curr, mask_pos, emb);

    // 2) projections
    gemm_bf16_kernel<<<dim3(32, 4), 512, GSMEM>>>(currhi, currlo, wkhi, wklo,
                                                  c_bk, pK, D_MODEL, D_MODEL, 0,
                                                  nullptr, nullptr);
    gemm_bf16_kernel<<<dim3(32, 4), 512, GSMEM>>>(currhi, currlo, wvhi, wvlo,
                                                  c_bv, pV, D_MODEL, D_MODEL, 0,
                                                  nullptr, nullptr);
    gemm_bf16_kernel<<<dim3(4, 4), 512, GSMEM>>>(qinhi, qinlo, wqhi, wqlo,
                                                 c_bq, pQm, D_MODEL, D_MODEL, 0,
                                                 nullptr, nullptr);

    // 3) attention
    attn_kernel<<<BATCH * HEADS, 128>>>();

    // 4) hyb = tanh(att) @ t2_w^T + t2_b
    tanh_split_kernel<<<W4 / 256, 256>>>(pAtt, t2ahi, t2alo, W4);
    gemm_bf16_kernel<<<dim3(4, 4), 512, GSMEM>>>(t2ahi, t2alo, twhi, twlo,
                                                 t2_b, pHyb, D_MODEL, D_MODEL, 0,
                                                 nullptr, nullptr);
    split_kernel<<<W4 / 256, 256>>>(pHyb, hybhi, hyblo, W4);

    // 5) scores + fused partial logsumexp
    gemm_bf16_kernel<<<dim3(4, NT_SCORES), 512, GSMEM>>>(
        hybhi, hyblo, embhi, emblo, nullptr, out, N_CAND, N_CAND, 1, pPm, pPs);

    // 6) finish log_softmax
    lse_reduce_kernel<<<M_GATH, 128>>>();
    {
        dim3 grid((N_CAND / 2 + 255) / 256, M_GATH);
        sub_kernel<<<grid, 256>>>(out);
    }
}